// round 7
// baseline (speedup 1.0000x reference)
#include <cuda_runtime.h>
#include <cstdint>

// Problem constants (fixed shapes)
#define BB   2
#define HD   4
#define HH   128
#define WW   128
#define KS   7
#define KK   49
#define NSP  9
#define SS   64
#define PLANE (HH * WW)
#define QF   196          // floats per (quad, head): 4 pixels * 49
#define QB   784          // bytes per (quad, head); 784 % 16 == 0

__device__ __forceinline__ uint32_t s2u(const void* p) {
    return (uint32_t)__cvta_generic_to_shared(p);
}

// Four pixels per warp: group g = lane>>3 -> pixel (h, w0+g).
// Lane t (=lane&7) owns k in {t, t+8, ..., t+40}; t==0 also owns k=48.
// attn is prefetched per-warp via cp.async.bulk (4 x 784B contiguous blocks,
// one per head) overlapped with the gather; out is written back via bulk S2G.
__global__ __launch_bounds__(128)
void attn_reweight_kernel(const float* __restrict__ attn,
                          const float* __restrict__ sims,
                          const int*   __restrict__ sinds,
                          float*       __restrict__ out)
{
    __shared__ alignas(16) float s_attn[4][HD][QF];
    __shared__ alignas(16) float s_out[4][2][QF];
    __shared__ alignas(8)  unsigned long long s_mbar[4];

    const int wwarp = threadIdx.x >> 5;
    const int lane  = threadIdx.x & 31;
    const int g     = lane >> 3;
    const int t     = lane & 7;

    const int warpid = blockIdx.x * 4 + wwarp;
    const int pix0 = warpid << 2;
    const int b    = pix0 >> 14;
    const int idx  = pix0 & 16383;
    const int h    = idx >> 7;
    const int w0   = idx & 127;          // multiple of 4
    const int w    = w0 + g;

    // quad base element for head 0: (((b*HD+0)*HH + h)*WW + w0) * KK
    const int quadElem0  = (((b * HD) * HH + h) * WW + w0) * KK;
    const int headStride = HH * WW * KK;

    const uint32_t mbar = s2u(&s_mbar[wwarp]);

    // ---- launch attn prefetch (4 heads x 784B) before the gather ----
    if (lane == 0) {
        asm volatile("mbarrier.init.shared.b64 [%0], 1;" :: "r"(mbar) : "memory");
        asm volatile("fence.proxy.async.shared::cta;" ::: "memory");
        asm volatile("mbarrier.arrive.expect_tx.shared.b64 _, [%0], %1;"
                     :: "r"(mbar), "r"(4 * QB) : "memory");
#pragma unroll
        for (int hd = 0; hd < HD; ++hd) {
            const float* src = attn + quadElem0 + hd * headStride;
            const uint32_t dst = s2u(&s_attn[wwarp][hd][0]);
            asm volatile(
                "cp.async.bulk.shared::cluster.global.mbarrier::complete_tx::bytes "
                "[%0], [%1], %2, [%3];"
                :: "r"(dst), "l"(src), "r"(QB), "r"(mbar) : "memory");
        }
    }
    __syncwarp();

    // ---- gather setup ----
    const int hs = min(max(h - KS / 2, 0), HH - KS);
    const int ws = min(max(w - KS / 2, 0), WW - KS);

    int off[6];
#pragma unroll
    for (int j = 0; j < 6; ++j) {
        const int k = 8 * j + t;
        off[j] = (hs + k / KS) * WW + ws + k % KS;
    }
    const int off6 = (hs + 6) * WW + (ws + 6);
    const bool l0  = (t == 0);

    const int cidx  = (h - hs) * KS + (w - ws);    // [0,48]
    const int slotc = cidx >> 3;
    const int srcl  = (g << 3) + (cidx & 7);

    const float* sb = sims + b * (SS * PLANE);

    // sinds: coalesced per-group loads, distribute via shfl
    const int sbase = (pix0 + g) * NSP;
    const int ind_a = __ldg(&sinds[sbase + t]);
    const int ind_b = l0 ? __ldg(&sinds[sbase + 8]) : 0;

    // ---- gather 9 planes ----
    float p[6][NSP], p6[NSP];
#pragma unroll
    for (int sp = 0; sp < NSP; ++sp) {
        const int gid = (sp < 8) ? __shfl_sync(0xffffffffu, ind_a, (g << 3) + sp)
                                 : __shfl_sync(0xffffffffu, ind_b, (g << 3));
        const float* pl = sb + gid * PLANE;
#pragma unroll
        for (int j = 0; j < 6; ++j)
            p[j][sp] = __ldg(&pl[off[j]]);
        p6[sp] = l0 ? __ldg(&pl[off6]) : 0.0f;
    }

    // ---- pi via shfl from the window (center always inside) ----
    float pi[NSP];
#pragma unroll
    for (int sp = 0; sp < NSP; ++sp) {
        const float val = (slotc == 0) ? p[0][sp]
                        : (slotc == 1) ? p[1][sp]
                        : (slotc == 2) ? p[2][sp]
                        : (slotc == 3) ? p[3][sp]
                        : (slotc == 4) ? p[4][sp]
                        : (slotc == 5) ? p[5][sp] : p6[sp];
        pi[sp] = __shfl_sync(0xffffffffu, val, srcl);
    }

    // ---- wait for attn prefetch ----
    {
        unsigned done = 0;
        while (!done) {
            asm volatile(
                "{\n\t.reg .pred p;\n\t"
                "mbarrier.try_wait.parity.acquire.cta.shared::cta.b64 p, [%1], %2, 0x989680;\n\t"
                "selp.b32 %0, 1, 0, p;\n\t}"
                : "=r"(done) : "r"(mbar), "r"(0u) : "memory");
        }
    }

    // ---- per-head compute ----
#pragma unroll
    for (int hd = 0; hd < HD; ++hd) {
        const float* sa = &s_attn[wwarp][hd][0];
        const int lbase = 49 * g;

        float a[6];
#pragma unroll
        for (int j = 0; j < 6; ++j)
            a[j] = __expf(sa[lbase + 8 * j + t]);
        const float a6 = __expf(l0 ? sa[lbase + 48] : -1e30f);  // 0 on t!=0

        // d[sp] = sum_k a_k * p_sp[k]  (8-lane butterfly)
        float d[NSP];
#pragma unroll
        for (int sp = 0; sp < NSP; ++sp) {
            float acc = fmaf(a[0], p[0][sp], a6 * p6[sp]);
#pragma unroll
            for (int j = 1; j < 6; ++j)
                acc = fmaf(a[j], p[j][sp], acc);
            d[sp] = acc;
        }
#pragma unroll
        for (int o = 4; o > 0; o >>= 1) {
#pragma unroll
            for (int sp = 0; sp < NSP; ++sp)
                d[sp] += __shfl_xor_sync(0xffffffffu, d[sp], o);
        }

        // w_sp = pi_sp / (eps + d_sp); paired reciprocals: 5 MUFU for 9 divides
        float wsp[NSP];
#pragma unroll
        for (int sp = 0; sp < NSP; ++sp)
            d[sp] += 1e-10f;
#pragma unroll
        for (int q = 0; q < 4; ++q) {
            const float prod = d[2 * q] * d[2 * q + 1];
            float rp;
            asm("rcp.approx.f32 %0, %1;" : "=f"(rp) : "f"(prod));
            wsp[2 * q]     = pi[2 * q]     * (rp * d[2 * q + 1]);
            wsp[2 * q + 1] = pi[2 * q + 1] * (rp * d[2 * q]);
        }
        {
            float r8;
            asm("rcp.approx.f32 %0, %1;" : "=f"(r8) : "f"(d[8]));
            wsp[8] = pi[8] * r8;
        }

        // out_k = a_k * sum_sp w_sp * p_sp[k]
        float o6 = 0.0f;
        float o[6];
#pragma unroll
        for (int j = 0; j < 6; ++j) o[j] = 0.0f;
#pragma unroll
        for (int sp = 0; sp < NSP; ++sp) {
#pragma unroll
            for (int j = 0; j < 6; ++j)
                o[j] = fmaf(wsp[sp], p[j][sp], o[j]);
            o6 = fmaf(wsp[sp], p6[sp], o6);
        }

        // ---- stage result into smem and bulk-store to global ----
        if (hd >= 2) {   // recycle double buffer: ensure its prior store drained
            if (lane == 0)
                asm volatile("cp.async.bulk.wait_group 1;" ::: "memory");
            __syncwarp();
        }
        float* so = &s_out[wwarp][hd & 1][0];
#pragma unroll
        for (int j = 0; j < 6; ++j)
            so[lbase + 8 * j + t] = a[j] * o[j];
        if (l0) so[lbase + 48] = a6 * o6;
        __syncwarp();
        asm volatile("fence.proxy.async.shared::cta;" ::: "memory");
        if (lane == 0) {
            float* gdst = out + quadElem0 + hd * headStride;
            const uint32_t ssrc = s2u(so);
            asm volatile("cp.async.bulk.global.shared::cta.bulk_group [%0], [%1], %2;"
                         :: "l"(gdst), "r"(ssrc), "r"(QB) : "memory");
            asm volatile("cp.async.bulk.commit_group;" ::: "memory");
        }
    }

    // drain all outstanding bulk stores before exit
    if (lane == 0)
        asm volatile("cp.async.bulk.wait_group 0;" ::: "memory");
}

extern "C" void kernel_launch(void* const* d_in, const int* in_sizes, int n_in,
                              void* d_out, int out_size)
{
    const float* attn  = (const float*)d_in[0];
    const float* sims  = (const float*)d_in[1];
    const int*   sinds = (const int*)d_in[2];
    float*       out   = (float*)d_out;

    const int warps   = BB * HH * WW / 4;        // 8192 warps (4 pixels each)
    const int threads = 128;                     // 4 warps / CTA
    const int blocks  = warps / (threads / 32);  // 2048
    attn_reweight_kernel<<<blocks, threads>>>(attn, sims, sinds, out);
}

// round 9
// speedup vs baseline: 1.0642x; 1.0642x over previous
#include <cuda_runtime.h>

// Problem constants (fixed shapes)
#define BB   2
#define HD   4
#define HH   128
#define WW   128
#define KS   7
#define KK   49
#define NSP  9
#define SS   64
#define PLANE (HH * WW)

// Four pixels per warp: group g = lane>>3 handles pixel (h, w0+g).
// Pair-ownership for vector ld/st: lane t owns k = 16j + 2t + par and k+1
// (j = 0..2), par = g&1 (alignment parity of the pixel's 49-float block).
// Straggler k = par ? 0 : 48 owned by t==0.
// Reductions: 8-lane xor butterfly (redux.add.f32 unsupported on sm_103).
// No max-subtraction: softmax-style ratio is scale-invariant in exp().
__global__ __launch_bounds__(128)
void attn_reweight_kernel(const float* __restrict__ attn,
                          const float* __restrict__ sims,
                          const int*   __restrict__ sinds,
                          float*       __restrict__ out)
{
    const int warpid = blockIdx.x * (blockDim.x >> 5) + (threadIdx.x >> 5);
    const int lane   = threadIdx.x & 31;
    const int g      = lane >> 3;
    const int t      = lane & 7;

    const int pix0 = warpid << 2;
    const int b    = pix0 >> 14;
    const int idx  = pix0 & 16383;
    const int h    = idx >> 7;
    const int w    = (idx & 127) + g;     // idx&127 multiple of 4
    const int par  = g & 1;               // alignment parity of 49*pixel

    const int hs = min(max(h - KS / 2, 0), HH - KS);
    const int ws = min(max(w - KS / 2, 0), WW - KS);

    // owned k values and their window offsets
    int off[6];
#pragma unroll
    for (int r = 0; r < 6; ++r) {
        const int k = 16 * (r >> 1) + 2 * t + (r & 1) + par;
        off[r] = (hs + k / KS) * WW + ws + k % KS;
    }
    const int  ksg  = par ? 0 : 48;                       // straggler k
    const int  offs = (hs + ksg / KS) * WW + ws + ksg % KS;
    const bool l0   = (t == 0);

    // center position inside window (uniform per group)
    const int  cidx  = (h - hs) * KS + (w - ws);          // [0,48]
    const bool cstrag = (cidx == ksg);
    const int  rp     = cidx - par;                       // >=0 when !cstrag
    const int  regc   = 2 * (rp >> 4) + (rp & 1);         // uniform per group
    const int  srcl   = (g << 3) + (cstrag ? 0 : ((rp & 15) >> 1));

    const float* sb = sims + b * (SS * PLANE);

    // sinds: coalesced per-group loads, distribute via shfl
    const int sbase = (pix0 + g) * NSP;
    const int ind_a = __ldg(&sinds[sbase + t]);
    const int ind_b = l0 ? __ldg(&sinds[sbase + 8]) : 0;

    // ---- gather 9 planes ----
    float p[6][NSP], p6[NSP];
#pragma unroll
    for (int sp = 0; sp < NSP; ++sp) {
        const int gid = (sp < 8) ? __shfl_sync(0xffffffffu, ind_a, (g << 3) + sp)
                                 : __shfl_sync(0xffffffffu, ind_b, (g << 3));
        const float* pl = sb + gid * PLANE;
#pragma unroll
        for (int r = 0; r < 6; ++r)
            p[r][sp] = __ldg(&pl[off[r]]);
        p6[sp] = l0 ? __ldg(&pl[offs]) : 0.0f;
    }

    // ---- pi via shfl from the window (center always inside) ----
    float pi[NSP];
#pragma unroll
    for (int sp = 0; sp < NSP; ++sp) {
        const float val = cstrag ? p6[sp]
                        : (regc == 0) ? p[0][sp]
                        : (regc == 1) ? p[1][sp]
                        : (regc == 2) ? p[2][sp]
                        : (regc == 3) ? p[3][sp]
                        : (regc == 4) ? p[4][sp] : p[5][sp];
        pi[sp] = __shfl_sync(0xffffffffu, val, srcl);
    }

    // ---- per-head compute ----
#pragma unroll
    for (int hd = 0; hd < HD; ++hd) {
        const int base = (((b * HD + hd) * HH + h) * WW + w) * KK;
        const float*  ab  = attn + base;
        const float2* ab2 = (const float2*)(ab + par);    // 8B-aligned by parity

        float a[6];
#pragma unroll
        for (int j = 0; j < 3; ++j) {
            const float2 v = __ldg(&ab2[8 * j + t]);      // k = 16j+2t+par, +1
            a[2 * j]     = __expf(v.x);
            a[2 * j + 1] = __expf(v.y);
        }
        const float a6 = __expf(l0 ? __ldg(ab + ksg) : -1e30f);   // 0 on t!=0

        // d[sp] = sum_k a_k * p_sp[k]; partial per lane, then 8-lane butterfly
        float d[NSP];
#pragma unroll
        for (int sp = 0; sp < NSP; ++sp) {
            float acc = fmaf(a[0], p[0][sp], a6 * p6[sp]);
#pragma unroll
            for (int r = 1; r < 6; ++r)
                acc = fmaf(a[r], p[r][sp], acc);
            d[sp] = acc;
        }
#pragma unroll
        for (int o = 4; o > 0; o >>= 1) {
#pragma unroll
            for (int sp = 0; sp < NSP; ++sp)
                d[sp] += __shfl_xor_sync(0xffffffffu, d[sp], o);
        }

        // w_sp = pi_sp / (eps + d_sp); paired reciprocals: 5 MUFU for 9 divides
        float wsp[NSP];
#pragma unroll
        for (int sp = 0; sp < NSP; ++sp)
            d[sp] += 1e-10f;
#pragma unroll
        for (int q = 0; q < 4; ++q) {
            const float prod = d[2 * q] * d[2 * q + 1];
            float rcp;
            asm("rcp.approx.f32 %0, %1;" : "=f"(rcp) : "f"(prod));
            wsp[2 * q]     = pi[2 * q]     * (rcp * d[2 * q + 1]);
            wsp[2 * q + 1] = pi[2 * q + 1] * (rcp * d[2 * q]);
        }
        {
            float r8;
            asm("rcp.approx.f32 %0, %1;" : "=f"(r8) : "f"(d[8]));
            wsp[8] = pi[8] * r8;
        }

        // out_k = a_k * sum_sp w_sp * p_sp[k]
        float o6 = 0.0f;
        float o[6];
#pragma unroll
        for (int r = 0; r < 6; ++r) o[r] = 0.0f;
#pragma unroll
        for (int sp = 0; sp < NSP; ++sp) {
#pragma unroll
            for (int r = 0; r < 6; ++r)
                o[r] = fmaf(wsp[sp], p[r][sp], o[r]);
            o6 = fmaf(wsp[sp], p6[sp], o6);
        }

        float2* ob2 = (float2*)(out + base + par);
#pragma unroll
        for (int j = 0; j < 3; ++j) {
            float2 vv;
            vv.x = a[2 * j]     * o[2 * j];
            vv.y = a[2 * j + 1] * o[2 * j + 1];
            ob2[8 * j + t] = vv;                          // STG.64
        }
        if (l0) out[base + ksg] = a6 * o6;
    }
}

extern "C" void kernel_launch(void* const* d_in, const int* in_sizes, int n_in,
                              void* d_out, int out_size)
{
    const float* attn  = (const float*)d_in[0];
    const float* sims  = (const float*)d_in[1];
    const int*   sinds = (const int*)d_in[2];
    float*       out   = (float*)d_out;

    const int warps   = BB * HH * WW / 4;        // 8192 warps (4 pixels each)
    const int threads = 128;                     // 4 warps / CTA
    const int blocks  = warps / (threads / 32);  // 2048
    attn_reweight_kernel<<<blocks, threads>>>(attn, sims, sinds, out);
}

// round 10
// speedup vs baseline: 1.0667x; 1.0023x over previous
#include <cuda_runtime.h>

// Problem constants (fixed shapes)
#define BB   2
#define HD   4
#define HH   128
#define WW   128
#define KS   7
#define KK   49
#define NSP  9
#define SS   64
#define PLANE (HH * WW)

// Four pixels per warp: group g = lane>>3 handles pixel (h, w0+g).
// Pair-ownership for vector ld/st: lane t owns k = 16j + 2t + par and k+1
// (j = 0..2), par = g&1 (alignment parity of the pixel's 49-float block).
// Straggler k = par ? 0 : 48 owned by t==0.
// Reductions: 8-lane xor butterfly. pi loaded directly (L1-hot broadcast).
// No max-subtraction: softmax-style ratio is scale-invariant in exp().
__global__ __launch_bounds__(128)
void attn_reweight_kernel(const float* __restrict__ attn,
                          const float* __restrict__ sims,
                          const int*   __restrict__ sinds,
                          float*       __restrict__ out)
{
    const int warpid = blockIdx.x * (blockDim.x >> 5) + (threadIdx.x >> 5);
    const int lane   = threadIdx.x & 31;
    const int g      = lane >> 3;
    const int t      = lane & 7;

    const int pix0 = warpid << 2;
    const int b    = pix0 >> 14;
    const int idx  = pix0 & 16383;
    const int h    = idx >> 7;
    const int w    = (idx & 127) + g;     // idx&127 multiple of 4
    const int par  = g & 1;               // alignment parity of 49*pixel

    const int hs = min(max(h - KS / 2, 0), HH - KS);
    const int ws = min(max(w - KS / 2, 0), WW - KS);

    // owned k values and their window offsets
    int off[6];
#pragma unroll
    for (int r = 0; r < 6; ++r) {
        const int k = 16 * (r >> 1) + 2 * t + (r & 1) + par;
        off[r] = (hs + k / KS) * WW + ws + k % KS;
    }
    const int  ksg  = par ? 0 : 48;                       // straggler k
    const int  offs = (hs + ksg / KS) * WW + ws + ksg % KS;
    const bool l0   = (t == 0);
    const float eps0 = l0 ? 1e-10f : 0.0f;                // eps seed, one lane/group

    const float* sb  = sims + b * (SS * PLANE);
    const int    offc = h * WW + w;                       // center (pi)

    // sinds: coalesced per-group loads, distribute via shfl
    const int sbase = (pix0 + g) * NSP;
    const int ind_a = __ldg(&sinds[sbase + t]);
    const int ind_b = l0 ? __ldg(&sinds[sbase + 8]) : 0;

    // ---- gather 9 planes (+ center pi, broadcast within group) ----
    float p[6][NSP], p6[NSP], pi[NSP];
#pragma unroll
    for (int sp = 0; sp < NSP; ++sp) {
        const int gid = (sp < 8) ? __shfl_sync(0xffffffffu, ind_a, (g << 3) + sp)
                                 : __shfl_sync(0xffffffffu, ind_b, (g << 3));
        const float* pl = sb + gid * PLANE;
#pragma unroll
        for (int r = 0; r < 6; ++r)
            p[r][sp] = __ldg(&pl[off[r]]);
        p6[sp] = l0 ? __ldg(&pl[offs]) : 0.0f;
        pi[sp] = __ldg(&pl[offc]);
    }

    // ---- per-head compute ----
#pragma unroll
    for (int hd = 0; hd < HD; ++hd) {
        const int base = (((b * HD + hd) * HH + h) * WW + w) * KK;
        const float*  ab  = attn + base;
        const float2* ab2 = (const float2*)(ab + par);    // 8B-aligned by parity

        float a[6];
#pragma unroll
        for (int j = 0; j < 3; ++j) {
            const float2 v = __ldg(&ab2[8 * j + t]);      // k = 16j+2t+par, +1
            a[2 * j]     = __expf(v.x);
            a[2 * j + 1] = __expf(v.y);
        }
        const float a6 = __expf(l0 ? __ldg(ab + ksg) : -1e30f);   // 0 on t!=0

        // d[sp] = eps + sum_k a_k * p_sp[k]; partial per lane, 8-lane butterfly
        float d[NSP];
#pragma unroll
        for (int sp = 0; sp < NSP; ++sp) {
            float acc = fmaf(a6, p6[sp], eps0);
#pragma unroll
            for (int r = 0; r < 6; ++r)
                acc = fmaf(a[r], p[r][sp], acc);
            d[sp] = acc;
        }
#pragma unroll
        for (int o = 4; o > 0; o >>= 1) {
#pragma unroll
            for (int sp = 0; sp < NSP; ++sp)
                d[sp] += __shfl_xor_sync(0xffffffffu, d[sp], o);
        }

        // w_sp = pi_sp / (eps + d_sp); paired reciprocals: 5 MUFU for 9 divides
        float wsp[NSP];
#pragma unroll
        for (int q = 0; q < 4; ++q) {
            const float prod = d[2 * q] * d[2 * q + 1];
            float rcp;
            asm("rcp.approx.f32 %0, %1;" : "=f"(rcp) : "f"(prod));
            wsp[2 * q]     = pi[2 * q]     * (rcp * d[2 * q + 1]);
            wsp[2 * q + 1] = pi[2 * q + 1] * (rcp * d[2 * q]);
        }
        {
            float r8;
            asm("rcp.approx.f32 %0, %1;" : "=f"(r8) : "f"(d[8]));
            wsp[8] = pi[8] * r8;
        }

        // out_k = a_k * sum_sp w_sp * p_sp[k]
        float o6 = 0.0f;
        float o[6];
#pragma unroll
        for (int r = 0; r < 6; ++r) o[r] = 0.0f;
#pragma unroll
        for (int sp = 0; sp < NSP; ++sp) {
#pragma unroll
            for (int r = 0; r < 6; ++r)
                o[r] = fmaf(wsp[sp], p[r][sp], o[r]);
            o6 = fmaf(wsp[sp], p6[sp], o6);
        }

        float2* ob2 = (float2*)(out + base + par);
#pragma unroll
        for (int j = 0; j < 3; ++j) {
            float2 vv;
            vv.x = a[2 * j]     * o[2 * j];
            vv.y = a[2 * j + 1] * o[2 * j + 1];
            ob2[8 * j + t] = vv;                          // STG.64
        }
        if (l0) out[base + ksg] = a6 * o6;
    }
}

extern "C" void kernel_launch(void* const* d_in, const int* in_sizes, int n_in,
                              void* d_out, int out_size)
{
    const float* attn  = (const float*)d_in[0];
    const float* sims  = (const float*)d_in[1];
    const int*   sinds = (const int*)d_in[2];
    float*       out   = (float*)d_out;

    const int warps   = BB * HH * WW / 4;        // 8192 warps (4 pixels each)
    const int threads = 128;                     // 4 warps / CTA
    const int blocks  = warps / (threads / 32);  // 2048
    attn_reweight_kernel<<<blocks, threads>>>(attn, sims, sinds, out);
}